// round 1
// baseline (speedup 1.0000x reference)
#include <cuda_runtime.h>
#include <cuda_bf16.h>

// out[i] = w_node * nodes[i, 0] + b_node   (pre-seeds the accumulator)
__global__ void tmp_init_kernel(const float* __restrict__ nodes,
                                const float* __restrict__ w_node_p,
                                const float* __restrict__ b_node_p,
                                float* __restrict__ out,
                                int n_nodes, int d_node) {
    int i = blockIdx.x * blockDim.x + threadIdx.x;
    if (i < n_nodes) {
        float wn = __ldg(w_node_p);
        float bn = __ldg(b_node_p);
        out[i] = wn * __ldg(nodes + (size_t)i * d_node) + bn;
    }
}

// Each thread handles 4 consecutive edges (int4-vectorized index loads),
// computes m = w_edge*edges[e,0] + w_node*nodes[senders[e],0],
// and RED-adds into out[receivers[e]].
__global__ void tmp_edge_kernel(const float* __restrict__ nodes,
                                const float* __restrict__ edges,
                                const int*   __restrict__ senders,
                                const int*   __restrict__ receivers,
                                const float* __restrict__ w_node_p,
                                const float* __restrict__ w_edge_p,
                                float* __restrict__ out,
                                int n_edges, int d_node, int d_edge) {
    const float wn = __ldg(w_node_p);
    const float we = __ldg(w_edge_p);

    int tid  = blockIdx.x * blockDim.x + threadIdx.x;
    int base = tid * 4;

    if (base + 3 < n_edges) {
        // Fast path: vectorized index loads (arrays are 16B-aligned harness allocs).
        int4 s4 = __ldg((const int4*)(senders)   + tid);
        int4 r4 = __ldg((const int4*)(receivers) + tid);

        // Issue all global loads up-front for MLP.
        float e0 = __ldg(edges + (size_t)(base + 0) * d_edge);
        float e1 = __ldg(edges + (size_t)(base + 1) * d_edge);
        float e2 = __ldg(edges + (size_t)(base + 2) * d_edge);
        float e3 = __ldg(edges + (size_t)(base + 3) * d_edge);

        float n0 = __ldg(nodes + (size_t)s4.x * d_node);
        float n1 = __ldg(nodes + (size_t)s4.y * d_node);
        float n2 = __ldg(nodes + (size_t)s4.z * d_node);
        float n3 = __ldg(nodes + (size_t)s4.w * d_node);

        atomicAdd(out + r4.x, fmaf(we, e0, wn * n0));
        atomicAdd(out + r4.y, fmaf(we, e1, wn * n1));
        atomicAdd(out + r4.z, fmaf(we, e2, wn * n2));
        atomicAdd(out + r4.w, fmaf(we, e3, wn * n3));
    } else {
        // Tail path
        for (int e = base; e < n_edges; ++e) {
            int s = __ldg(senders + e);
            int r = __ldg(receivers + e);
            float ev = __ldg(edges + (size_t)e * d_edge);
            float nv = __ldg(nodes + (size_t)s * d_node);
            atomicAdd(out + r, fmaf(we, ev, wn * nv));
        }
    }
}

extern "C" void kernel_launch(void* const* d_in, const int* in_sizes, int n_in,
                              void* d_out, int out_size) {
    const float* nodes     = (const float*)d_in[0];
    const float* edges     = (const float*)d_in[1];
    const int*   senders   = (const int*)  d_in[2];
    const int*   receivers = (const int*)  d_in[3];
    const float* w_node    = (const float*)d_in[4];
    const float* w_edge    = (const float*)d_in[5];
    const float* b_node    = (const float*)d_in[6];
    float*       out       = (float*)d_out;

    const int n_nodes = out_size;
    const int n_edges = in_sizes[2];
    const int d_node  = in_sizes[0] / n_nodes;   // 128
    const int d_edge  = in_sizes[1] / n_edges;   // 16

    // 1) Seed output with w_node*nodes[:,0] + b_node
    {
        int threads = 256;
        int blocks  = (n_nodes + threads - 1) / threads;
        tmp_init_kernel<<<blocks, threads>>>(nodes, w_node, b_node, out, n_nodes, d_node);
    }

    // 2) Scatter-add messages (4 edges per thread)
    {
        int threads = 256;
        int edges_per_block = threads * 4;
        int blocks = (n_edges + edges_per_block - 1) / edges_per_block;
        tmp_edge_kernel<<<blocks, threads>>>(nodes, edges, senders, receivers,
                                             w_node, w_edge, out,
                                             n_edges, d_node, d_edge);
    }
}